// round 4
// baseline (speedup 1.0000x reference)
#include <cuda_runtime.h>
#include <math.h>

#define SQ      2048
#define Dm      512
#define NHEADS  8
#define HDIM    64
#define MTOT    8192
#define SCLOG   (0.125f * 1.44269504f)

__device__ float g_Q [MTOT * Dm];
__device__ float g_K [MTOT * Dm];
__device__ float g_V [MTOT * Dm];
__device__ float g_O1[MTOT * Dm];

__device__ __forceinline__ unsigned f2tf(float x) {
    unsigned u;
    asm("cvt.rna.tf32.f32 %0, %1;" : "=r"(u) : "f"(x));
    return u;
}

__device__ __forceinline__ void mma8(float* c, unsigned a0, unsigned a1,
                                     unsigned a2, unsigned a3,
                                     unsigned b0, unsigned b1) {
    asm volatile(
        "mma.sync.aligned.m16n8k8.row.col.f32.tf32.tf32.f32 "
        "{%0,%1,%2,%3}, {%4,%5,%6,%7}, {%8,%9}, {%0,%1,%2,%3};\n"
        : "+f"(c[0]), "+f"(c[1]), "+f"(c[2]), "+f"(c[3])
        : "r"(a0), "r"(a1), "r"(a2), "r"(a3), "r"(b0), "r"(b1));
}

// ---------------------------------------------------------------------------
// tf32 GEMM body: out = X.W^T + bias (MODE 0) / res + relu(...) (MODE 1)
// 128x128 tile, 8 warps as 4m x 2n, warp = 32 rows x 64 cols.
// ---------------------------------------------------------------------------
template<int MODE>
__device__ __forceinline__ void gemm_body(
    const float* __restrict__ X, const float* __restrict__ W,
    const float* __restrict__ bias, const float* __restrict__ res,
    float* __restrict__ out, int m0, int n0)
{
    __shared__ unsigned Xs[128][36];   // [m][k]
    __shared__ unsigned Ws[128][36];   // [n][k]

    const int tid  = threadIdx.x;
    const int wid  = tid >> 5;
    const int lane = tid & 31;
    const int g    = lane >> 2;
    const int tig  = lane & 3;
    const int wm   = wid >> 1;
    const int wn   = wid & 1;

    float acc[2][8][4];
#pragma unroll
    for (int s = 0; s < 2; s++)
#pragma unroll
        for (int i = 0; i < 8; i++)
#pragma unroll
            for (int j = 0; j < 4; j++) acc[s][i][j] = 0.f;

    for (int k0 = 0; k0 < Dm; k0 += 32) {
        __syncthreads();
#pragma unroll
        for (int i = 0; i < 4; i++) {
            int idx = tid + 256 * i;
            int r   = idx >> 3;
            int c4  = (idx & 7) * 4;
            float4 xv = *(const float4*)&X[(size_t)(m0 + r) * Dm + k0 + c4];
            *(uint4*)&Xs[r][c4] =
                make_uint4(f2tf(xv.x), f2tf(xv.y), f2tf(xv.z), f2tf(xv.w));
            float4 wv = *(const float4*)&W[(size_t)(n0 + r) * Dm + k0 + c4];
            *(uint4*)&Ws[r][c4] =
                make_uint4(f2tf(wv.x), f2tf(wv.y), f2tf(wv.z), f2tf(wv.w));
        }
        __syncthreads();

#pragma unroll
        for (int kk = 0; kk < 4; kk++) {
            const int kb = kk * 8;
            unsigned a[2][4];
#pragma unroll
            for (int s = 0; s < 2; s++) {
                const int rr = wm * 32 + s * 16 + g;
                a[s][0] = Xs[rr][kb + tig];
                a[s][1] = Xs[rr + 8][kb + tig];
                a[s][2] = Xs[rr][kb + tig + 4];
                a[s][3] = Xs[rr + 8][kb + tig + 4];
            }
#pragma unroll
            for (int nt = 0; nt < 8; nt++) {
                const int nr = wn * 64 + nt * 8 + g;
                unsigned b0 = Ws[nr][kb + tig];
                unsigned b1 = Ws[nr][kb + tig + 4];
                mma8(acc[0][nt], a[0][0], a[0][1], a[0][2], a[0][3], b0, b1);
                mma8(acc[1][nt], a[1][0], a[1][1], a[1][2], a[1][3], b0, b1);
            }
        }
    }

#pragma unroll
    for (int s = 0; s < 2; s++) {
        const int r0 = m0 + wm * 32 + s * 16 + g;
        const int r1 = r0 + 8;
#pragma unroll
        for (int nt = 0; nt < 8; nt++) {
            const int n = n0 + wn * 64 + nt * 8 + 2 * tig;
            float2 bz = *(const float2*)&bias[n];
            float2 o0, o1;
            o0.x = acc[s][nt][0] + bz.x; o0.y = acc[s][nt][1] + bz.y;
            o1.x = acc[s][nt][2] + bz.x; o1.y = acc[s][nt][3] + bz.y;
            if (MODE == 1) {
                float2 q0 = *(const float2*)&res[(size_t)r0 * Dm + n];
                float2 q1 = *(const float2*)&res[(size_t)r1 * Dm + n];
                o0.x = q0.x + fmaxf(o0.x, 0.f); o0.y = q0.y + fmaxf(o0.y, 0.f);
                o1.x = q1.x + fmaxf(o1.x, 0.f); o1.y = q1.y + fmaxf(o1.y, 0.f);
            }
            *(float2*)&out[(size_t)r0 * Dm + n] = o0;
            *(float2*)&out[(size_t)r1 * Dm + n] = o1;
        }
    }
}

// Fused Q/K/V projection: blockIdx.z selects which projection.
__global__ void __launch_bounds__(256) gemm_qkv(
    const float* __restrict__ query, const float* __restrict__ keyv,
    const float* __restrict__ Wq, const float* __restrict__ bq,
    const float* __restrict__ Wk, const float* __restrict__ bk,
    const float* __restrict__ Wv, const float* __restrict__ bv,
    float* __restrict__ oq, float* __restrict__ ok, float* __restrict__ ov)
{
    const int z = blockIdx.z;
    const float* X = (z == 0) ? query : keyv;
    const float* W = (z == 0) ? Wq : (z == 1) ? Wk : Wv;
    const float* B = (z == 0) ? bq : (z == 1) ? bk : bv;
    float* out     = (z == 0) ? oq : (z == 1) ? ok : ov;
    gemm_body<0>(X, W, B, nullptr, out, blockIdx.x * 128, blockIdx.y * 128);
}

__global__ void __launch_bounds__(256) gemm_out(
    const float* __restrict__ X, const float* __restrict__ W,
    const float* __restrict__ bias, const float* __restrict__ res,
    float* __restrict__ out)
{
    gemm_body<1>(X, W, bias, res, out, blockIdx.x * 128, blockIdx.y * 128);
}

// ---------------------------------------------------------------------------
// tf32 flash attention: CTA = 128q x 64kv, 4 warps, warp owns 32 q rows
// (2 strips of 16) => every K/V B-fragment feeds 2 mmas. 3 CTAs/SM.
// Softmax scale folded into Q staging. P stays in registers (quad shuffles).
// ---------------------------------------------------------------------------
#define BKV 64
#define QS_STRIDE 68
#define KS_STRIDE 68
#define VS_STRIDE 72
#define QS_BASE 0
#define KS_BASE (QS_BASE + 128 * QS_STRIDE)
#define VS_BASE (KS_BASE + BKV * KS_STRIDE)
#define FLASH_SMEM_U32 (VS_BASE + BKV * VS_STRIDE)
#define FLASH_SMEM_BYTES (FLASH_SMEM_U32 * 4)

__global__ void __launch_bounds__(128, 3) flash_tc(
    const float* __restrict__ gQ, const float* __restrict__ gK,
    const float* __restrict__ gV, float* __restrict__ gO1)
{
    extern __shared__ unsigned sm[];
    unsigned* Qs = sm + QS_BASE;   // [128][68] q*SCLOG tf32, [m][d]
    unsigned* Ks = sm + KS_BASE;   // [64][68]  k tf32, [kv][d]
    unsigned* Vs = sm + VS_BASE;   // [64][72]  v tf32, [kv][d]

    const int tid  = threadIdx.x;
    const int wid  = tid >> 5;
    const int lane = tid & 31;
    const int g    = lane >> 2;
    const int tig  = lane & 3;

    const int bh = blockIdx.y;
    const int b  = bh / NHEADS;
    const int h  = bh % NHEADS;
    const int q0 = blockIdx.x * 128;

    const float* Qg = gQ + ((size_t)b * SQ + q0) * Dm + h * HDIM;
    const float* Kg = gK + (size_t)b * SQ * Dm + h * HDIM;
    const float* Vg = gV + (size_t)b * SQ * Dm + h * HDIM;

    // Stage Q tile once, pre-scaled by SCLOG
#pragma unroll
    for (int i = 0; i < 16; i++) {
        int idx = tid + 128 * i;
        int r   = idx >> 4;
        int c4  = (idx & 15) * 4;
        float4 v = *(const float4*)&Qg[(size_t)r * Dm + c4];
        *(uint4*)&Qs[r * QS_STRIDE + c4] =
            make_uint4(f2tf(v.x * SCLOG), f2tf(v.y * SCLOG),
                       f2tf(v.z * SCLOG), f2tf(v.w * SCLOG));
    }

    float mst[4] = {-1e30f, -1e30f, -1e30f, -1e30f};   // [strip*2 + half]
    float lst[4] = {0.f, 0.f, 0.f, 0.f};
    float oacc[2][8][4];
#pragma unroll
    for (int s = 0; s < 2; s++)
#pragma unroll
        for (int i = 0; i < 8; i++)
#pragma unroll
            for (int j = 0; j < 4; j++) oacc[s][i][j] = 0.f;

    const int rbase  = wid * 32;
    const int s0lane = (lane & ~3) | (tig >> 1);
    const int s1lane = s0lane + 2;
    const bool odd   = tig & 1;

    for (int kv0 = 0; kv0 < SQ; kv0 += BKV) {
        __syncthreads();
#pragma unroll
        for (int i = 0; i < 8; i++) {
            int idx = tid + 128 * i;
            int r   = idx >> 4;
            int c4  = (idx & 15) * 4;
            float4 kv = *(const float4*)&Kg[(size_t)(kv0 + r) * Dm + c4];
            *(uint4*)&Ks[r * KS_STRIDE + c4] =
                make_uint4(f2tf(kv.x), f2tf(kv.y), f2tf(kv.z), f2tf(kv.w));
            float4 vv = *(const float4*)&Vg[(size_t)(kv0 + r) * Dm + c4];
            *(uint4*)&Vs[r * VS_STRIDE + c4] =
                make_uint4(f2tf(vv.x), f2tf(vv.y), f2tf(vv.z), f2tf(vv.w));
        }
        __syncthreads();

        // S = (Q*SCLOG) K^T   (2 strips x 64 kv cols)
        float sacc[2][8][4];
#pragma unroll
        for (int s = 0; s < 2; s++)
#pragma unroll
            for (int i = 0; i < 8; i++)
#pragma unroll
                for (int j = 0; j < 4; j++) sacc[s][i][j] = 0.f;

#pragma unroll
        for (int ks = 0; ks < 8; ks++) {
            const int kb = ks * 8;
            unsigned a[2][4];
#pragma unroll
            for (int s = 0; s < 2; s++) {
                const int base = (rbase + s * 16 + g) * QS_STRIDE + kb;
                a[s][0] = Qs[base + tig];
                a[s][1] = Qs[base + 8 * QS_STRIDE + tig];
                a[s][2] = Qs[base + tig + 4];
                a[s][3] = Qs[base + 8 * QS_STRIDE + tig + 4];
            }
#pragma unroll
            for (int nt = 0; nt < 8; nt++) {
                const int rowb = (nt * 8 + g) * KS_STRIDE + kb;
                unsigned b0 = Ks[rowb + tig];
                unsigned b1 = Ks[rowb + tig + 4];
                mma8(sacc[0][nt], a[0][0], a[0][1], a[0][2], a[0][3], b0, b1);
                mma8(sacc[1][nt], a[1][0], a[1][1], a[1][2], a[1][3], b0, b1);
            }
        }

        // Online softmax per strip (values already in log2 domain)
#pragma unroll
        for (int s = 0; s < 2; s++) {
            float mx0 = -1e30f, mx1 = -1e30f;
#pragma unroll
            for (int nt = 0; nt < 8; nt++) {
                mx0 = fmaxf(mx0, fmaxf(sacc[s][nt][0], sacc[s][nt][1]));
                mx1 = fmaxf(mx1, fmaxf(sacc[s][nt][2], sacc[s][nt][3]));
            }
            mx0 = fmaxf(mx0, __shfl_xor_sync(0xffffffffu, mx0, 1));
            mx0 = fmaxf(mx0, __shfl_xor_sync(0xffffffffu, mx0, 2));
            mx1 = fmaxf(mx1, __shfl_xor_sync(0xffffffffu, mx1, 1));
            mx1 = fmaxf(mx1, __shfl_xor_sync(0xffffffffu, mx1, 2));

            float mn0 = fmaxf(mst[2 * s], mx0);
            float mn1 = fmaxf(mst[2 * s + 1], mx1);
            float al0 = exp2f(mst[2 * s] - mn0);
            float al1 = exp2f(mst[2 * s + 1] - mn1);
            mst[2 * s] = mn0; mst[2 * s + 1] = mn1;

            float sum0 = 0.f, sum1 = 0.f;
#pragma unroll
            for (int nt = 0; nt < 8; nt++) {
                float p00 = exp2f(sacc[s][nt][0] - mn0);
                float p01 = exp2f(sacc[s][nt][1] - mn0);
                float p10 = exp2f(sacc[s][nt][2] - mn1);
                float p11 = exp2f(sacc[s][nt][3] - mn1);
                sum0 += p00 + p01;
                sum1 += p10 + p11;
                sacc[s][nt][0] = p00; sacc[s][nt][1] = p01;
                sacc[s][nt][2] = p10; sacc[s][nt][3] = p11;
            }
            sum0 += __shfl_xor_sync(0xffffffffu, sum0, 1);
            sum0 += __shfl_xor_sync(0xffffffffu, sum0, 2);
            sum1 += __shfl_xor_sync(0xffffffffu, sum1, 1);
            sum1 += __shfl_xor_sync(0xffffffffu, sum1, 2);
            lst[2 * s]     = lst[2 * s] * al0 + sum0;
            lst[2 * s + 1] = lst[2 * s + 1] * al1 + sum1;

#pragma unroll
            for (int nt = 0; nt < 8; nt++) {
                oacc[s][nt][0] *= al0; oacc[s][nt][1] *= al0;
                oacc[s][nt][2] *= al1; oacc[s][nt][3] *= al1;
            }
        }

        // O += P V : A-fragments from S C-fragments via quad shuffles
#pragma unroll
        for (int ks = 0; ks < 8; ks++) {
            const int kb = ks * 8;
            unsigned af[2][4];
#pragma unroll
            for (int s = 0; s < 2; s++) {
                float c0 = sacc[s][ks][0], c1 = sacc[s][ks][1];
                float c2 = sacc[s][ks][2], c3 = sacc[s][ks][3];
                float u00 = __shfl_sync(0xffffffffu, c0, s0lane);
                float u01 = __shfl_sync(0xffffffffu, c1, s0lane);
                float u10 = __shfl_sync(0xffffffffu, c0, s1lane);
                float u11 = __shfl_sync(0xffffffffu, c1, s1lane);
                float w00 = __shfl_sync(0xffffffffu, c2, s0lane);
                float w01 = __shfl_sync(0xffffffffu, c3, s0lane);
                float w10 = __shfl_sync(0xffffffffu, c2, s1lane);
                float w11 = __shfl_sync(0xffffffffu, c3, s1lane);
                af[s][0] = f2tf(odd ? u01 : u00);
                af[s][2] = f2tf(odd ? u11 : u10);
                af[s][1] = f2tf(odd ? w01 : w00);
                af[s][3] = f2tf(odd ? w11 : w10);
            }
#pragma unroll
            for (int nt = 0; nt < 8; nt++) {
                unsigned b0 = Vs[(kb + tig) * VS_STRIDE + nt * 8 + g];
                unsigned b1 = Vs[(kb + tig + 4) * VS_STRIDE + nt * 8 + g];
                mma8(oacc[0][nt], af[0][0], af[0][1], af[0][2], af[0][3], b0, b1);
                mma8(oacc[1][nt], af[1][0], af[1][1], af[1][2], af[1][3], b0, b1);
            }
        }
    }

    // Epilogue: out1 = q(fp32) + O/l
    float* Og = gO1 + ((size_t)b * SQ + q0) * Dm + h * HDIM;
#pragma unroll
    for (int s = 0; s < 2; s++) {
        const int r0 = rbase + s * 16 + g;
        const int r1 = r0 + 8;
        const float li0 = 1.f / lst[2 * s];
        const float li1 = 1.f / lst[2 * s + 1];
#pragma unroll
        for (int nt = 0; nt < 8; nt++) {
            const int c = nt * 8 + 2 * tig;
            float2 q0v = *(const float2*)&Qg[(size_t)r0 * Dm + c];
            float2 q1v = *(const float2*)&Qg[(size_t)r1 * Dm + c];
            float2 o0, o1;
            o0.x = q0v.x + oacc[s][nt][0] * li0;
            o0.y = q0v.y + oacc[s][nt][1] * li0;
            o1.x = q1v.x + oacc[s][nt][2] * li1;
            o1.y = q1v.y + oacc[s][nt][3] * li1;
            *(float2*)&Og[(size_t)r0 * Dm + c] = o0;
            *(float2*)&Og[(size_t)r1 * Dm + c] = o1;
        }
    }
}

// ---------------------------------------------------------------------------
extern "C" void kernel_launch(void* const* d_in, const int* in_sizes, int n_in,
                              void* d_out, int out_size)
{
    const float* query = (const float*)d_in[0];
    const float* keyv  = (const float*)d_in[1];
    const float* Wq    = (const float*)d_in[2];
    const float* bq    = (const float*)d_in[3];
    const float* Wk    = (const float*)d_in[4];
    const float* bk    = (const float*)d_in[5];
    const float* Wv    = (const float*)d_in[6];
    const float* bv    = (const float*)d_in[7];
    const float* Wo    = (const float*)d_in[8];
    const float* bo    = (const float*)d_in[9];
    float* out = (float*)d_out;

    float *qb, *kb, *vb, *o1;
    cudaGetSymbolAddress((void**)&qb, g_Q);
    cudaGetSymbolAddress((void**)&kb, g_K);
    cudaGetSymbolAddress((void**)&vb, g_V);
    cudaGetSymbolAddress((void**)&o1, g_O1);

    cudaFuncSetAttribute(flash_tc,
                         cudaFuncAttributeMaxDynamicSharedMemorySize,
                         FLASH_SMEM_BYTES);

    dim3 gq(MTOT / 128, Dm / 128, 3);   // (64, 4, 3)
    gemm_qkv<<<gq, 256>>>(query, keyv, Wq, bq, Wk, bk, Wv, bv, qb, kb, vb);

    dim3 ga(SQ / 128, 4 * NHEADS);      // (16, 32)
    flash_tc<<<ga, 128, FLASH_SMEM_BYTES>>>(qb, kb, vb, o1);

    dim3 gg(MTOT / 128, Dm / 128);      // (64, 4)
    gemm_out<<<gg, 256>>>(o1, Wo, bo, o1, out);
}

// round 5
// speedup vs baseline: 1.4675x; 1.4675x over previous
#include <cuda_runtime.h>
#include <cuda_bf16.h>
#include <math.h>

#define SQ      2048
#define Dm      512
#define NHEADS  8
#define HDIM    64
#define MTOT    8192
#define SCLOG   (0.125f * 1.44269504f)

__device__ float g_Q [MTOT * Dm];
__device__ float g_K [MTOT * Dm];
__device__ float g_V [MTOT * Dm];
__device__ float g_O1[MTOT * Dm];

__device__ __forceinline__ unsigned f2tf(float x) {
    unsigned u;
    asm("cvt.rna.tf32.f32 %0, %1;" : "=r"(u) : "f"(x));
    return u;
}
// pack(lo, hi): lo -> low 16 bits, hi -> high 16 bits
__device__ __forceinline__ unsigned pkbf(float lo, float hi) {
    unsigned u;
    asm("cvt.rn.bf16x2.f32 %0, %1, %2;" : "=r"(u) : "f"(hi), "f"(lo));
    return u;
}

__device__ __forceinline__ void mma8(float* c, unsigned a0, unsigned a1,
                                     unsigned a2, unsigned a3,
                                     unsigned b0, unsigned b1) {
    asm volatile(
        "mma.sync.aligned.m16n8k8.row.col.f32.tf32.tf32.f32 "
        "{%0,%1,%2,%3}, {%4,%5,%6,%7}, {%8,%9}, {%0,%1,%2,%3};\n"
        : "+f"(c[0]), "+f"(c[1]), "+f"(c[2]), "+f"(c[3])
        : "r"(a0), "r"(a1), "r"(a2), "r"(a3), "r"(b0), "r"(b1));
}
__device__ __forceinline__ void mma16bf(float* c, unsigned a0, unsigned a1,
                                        unsigned a2, unsigned a3,
                                        unsigned b0, unsigned b1) {
    asm volatile(
        "mma.sync.aligned.m16n8k16.row.col.f32.bf16.bf16.f32 "
        "{%0,%1,%2,%3}, {%4,%5,%6,%7}, {%8,%9}, {%0,%1,%2,%3};\n"
        : "+f"(c[0]), "+f"(c[1]), "+f"(c[2]), "+f"(c[3])
        : "r"(a0), "r"(a1), "r"(a2), "r"(a3), "r"(b0), "r"(b1));
}

// ---------------------------------------------------------------------------
// tf32 GEMM body (unchanged from R4): 128x128 tile, 8 warps as 4m x 2n.
// ---------------------------------------------------------------------------
template<int MODE>
__device__ __forceinline__ void gemm_body(
    const float* __restrict__ X, const float* __restrict__ W,
    const float* __restrict__ bias, const float* __restrict__ res,
    float* __restrict__ out, int m0, int n0)
{
    __shared__ unsigned Xs[128][36];
    __shared__ unsigned Ws[128][36];

    const int tid  = threadIdx.x;
    const int wid  = tid >> 5;
    const int lane = tid & 31;
    const int g    = lane >> 2;
    const int tig  = lane & 3;
    const int wm   = wid >> 1;
    const int wn   = wid & 1;

    float acc[2][8][4];
#pragma unroll
    for (int s = 0; s < 2; s++)
#pragma unroll
        for (int i = 0; i < 8; i++)
#pragma unroll
            for (int j = 0; j < 4; j++) acc[s][i][j] = 0.f;

    for (int k0 = 0; k0 < Dm; k0 += 32) {
        __syncthreads();
#pragma unroll
        for (int i = 0; i < 4; i++) {
            int idx = tid + 256 * i;
            int r   = idx >> 3;
            int c4  = (idx & 7) * 4;
            float4 xv = *(const float4*)&X[(size_t)(m0 + r) * Dm + k0 + c4];
            *(uint4*)&Xs[r][c4] =
                make_uint4(f2tf(xv.x), f2tf(xv.y), f2tf(xv.z), f2tf(xv.w));
            float4 wv = *(const float4*)&W[(size_t)(n0 + r) * Dm + k0 + c4];
            *(uint4*)&Ws[r][c4] =
                make_uint4(f2tf(wv.x), f2tf(wv.y), f2tf(wv.z), f2tf(wv.w));
        }
        __syncthreads();

#pragma unroll
        for (int kk = 0; kk < 4; kk++) {
            const int kb = kk * 8;
            unsigned a[2][4];
#pragma unroll
            for (int s = 0; s < 2; s++) {
                const int rr = wm * 32 + s * 16 + g;
                a[s][0] = Xs[rr][kb + tig];
                a[s][1] = Xs[rr + 8][kb + tig];
                a[s][2] = Xs[rr][kb + tig + 4];
                a[s][3] = Xs[rr + 8][kb + tig + 4];
            }
#pragma unroll
            for (int nt = 0; nt < 8; nt++) {
                const int nr = wn * 64 + nt * 8 + g;
                unsigned b0 = Ws[nr][kb + tig];
                unsigned b1 = Ws[nr][kb + tig + 4];
                mma8(acc[0][nt], a[0][0], a[0][1], a[0][2], a[0][3], b0, b1);
                mma8(acc[1][nt], a[1][0], a[1][1], a[1][2], a[1][3], b0, b1);
            }
        }
    }

#pragma unroll
    for (int s = 0; s < 2; s++) {
        const int r0 = m0 + wm * 32 + s * 16 + g;
        const int r1 = r0 + 8;
#pragma unroll
        for (int nt = 0; nt < 8; nt++) {
            const int n = n0 + wn * 64 + nt * 8 + 2 * tig;
            float2 bz = *(const float2*)&bias[n];
            float2 o0, o1;
            o0.x = acc[s][nt][0] + bz.x; o0.y = acc[s][nt][1] + bz.y;
            o1.x = acc[s][nt][2] + bz.x; o1.y = acc[s][nt][3] + bz.y;
            if (MODE == 1) {
                float2 q0 = *(const float2*)&res[(size_t)r0 * Dm + n];
                float2 q1 = *(const float2*)&res[(size_t)r1 * Dm + n];
                o0.x = q0.x + fmaxf(o0.x, 0.f); o0.y = q0.y + fmaxf(o0.y, 0.f);
                o1.x = q1.x + fmaxf(o1.x, 0.f); o1.y = q1.y + fmaxf(o1.y, 0.f);
            }
            *(float2*)&out[(size_t)r0 * Dm + n] = o0;
            *(float2*)&out[(size_t)r1 * Dm + n] = o1;
        }
    }
}

__global__ void __launch_bounds__(256) gemm_qkv(
    const float* __restrict__ query, const float* __restrict__ keyv,
    const float* __restrict__ Wq, const float* __restrict__ bq,
    const float* __restrict__ Wk, const float* __restrict__ bk,
    const float* __restrict__ Wv, const float* __restrict__ bv,
    float* __restrict__ oq, float* __restrict__ ok, float* __restrict__ ov)
{
    const int z = blockIdx.z;
    const float* X = (z == 0) ? query : keyv;
    const float* W = (z == 0) ? Wq : (z == 1) ? Wk : Wv;
    const float* B = (z == 0) ? bq : (z == 1) ? bk : bv;
    float* out     = (z == 0) ? oq : (z == 1) ? ok : ov;
    gemm_body<0>(X, W, B, nullptr, out, blockIdx.x * 128, blockIdx.y * 128);
}

__global__ void __launch_bounds__(256) gemm_out(
    const float* __restrict__ X, const float* __restrict__ W,
    const float* __restrict__ bias, const float* __restrict__ res,
    float* __restrict__ out)
{
    gemm_body<1>(X, W, bias, res, out, blockIdx.x * 128, blockIdx.y * 128);
}

// ---------------------------------------------------------------------------
// bf16 flash attention: 128q x 128kv, 8 warps (warp = 16 q rows), 2 CTAs/SM.
//  - Q (pre-scaled by SCLOG) / K in bf16 [row][d], u32 stride 36 (banks 4g+tig)
//  - V kv-pair-packed: PB[kvpair][d] = bf16x2(V[2r][d], V[2r+1][d]), stride 72
//    (banks 8*tig+g). PV B-fragment = single LDS.32.
//  - P: S C-frag == PV A-frag layout -> register packs, no smem, no shuffles.
// ---------------------------------------------------------------------------
#define QK_STRIDE 36
#define PB_STRIDE 72
#define QS_BASE 0
#define KS_BASE (128 * QK_STRIDE)
#define PB_BASE (KS_BASE + 128 * QK_STRIDE)
#define FLASH_SMEM_U32 (PB_BASE + 64 * PB_STRIDE)
#define FLASH_SMEM_BYTES (FLASH_SMEM_U32 * 4)

__global__ void __launch_bounds__(256, 2) flash_tc(
    const float* __restrict__ gQ, const float* __restrict__ gK,
    const float* __restrict__ gV, float* __restrict__ gO1)
{
    extern __shared__ unsigned sm[];
    unsigned* Qs = sm + QS_BASE;   // [128][36] bf16x2 pairs of q*SCLOG
    unsigned* Ks = sm + KS_BASE;   // [128][36] bf16x2 pairs of k
    unsigned* PB = sm + PB_BASE;   // [64][72]  bf16x2 (V[2r][d], V[2r+1][d])

    const int tid  = threadIdx.x;
    const int wid  = tid >> 5;
    const int lane = tid & 31;
    const int g    = lane >> 2;
    const int tig  = lane & 3;

    const int bh = blockIdx.y;
    const int b  = bh / NHEADS;
    const int h  = bh % NHEADS;
    const int q0 = blockIdx.x * 128;

    const float* Qg = gQ + ((size_t)b * SQ + q0) * Dm + h * HDIM;
    const float* Kg = gK + (size_t)b * SQ * Dm + h * HDIM;
    const float* Vg = gV + (size_t)b * SQ * Dm + h * HDIM;

    // Stage Q once: bf16(q * SCLOG)
#pragma unroll
    for (int i = 0; i < 8; i++) {
        int idx = tid + 256 * i;
        int r   = idx >> 4;
        int c4  = (idx & 15) * 4;
        float4 v = *(const float4*)&Qg[(size_t)r * Dm + c4];
        Qs[r * QK_STRIDE + (c4 >> 1)]     = pkbf(v.x * SCLOG, v.y * SCLOG);
        Qs[r * QK_STRIDE + (c4 >> 1) + 1] = pkbf(v.z * SCLOG, v.w * SCLOG);
    }

    float m0r = -1e30f, m1r = -1e30f, l0 = 0.f, l1 = 0.f;
    float oacc[8][4];
#pragma unroll
    for (int i = 0; i < 8; i++)
#pragma unroll
        for (int j = 0; j < 4; j++) oacc[i][j] = 0.f;

    const int rw0 = 16 * wid + g;
    const int rw1 = rw0 + 8;

    for (int kv0 = 0; kv0 < SQ; kv0 += 128) {
        __syncthreads();
        // K staging: bf16 row-major
#pragma unroll
        for (int i = 0; i < 8; i++) {
            int idx = tid + 256 * i;
            int r   = idx >> 4;
            int c4  = (idx & 15) * 4;
            float4 kv = *(const float4*)&Kg[(size_t)(kv0 + r) * Dm + c4];
            Ks[r * QK_STRIDE + (c4 >> 1)]     = pkbf(kv.x, kv.y);
            Ks[r * QK_STRIDE + (c4 >> 1) + 1] = pkbf(kv.z, kv.w);
        }
        // V staging: kv-pair packed
#pragma unroll
        for (int i = 0; i < 4; i++) {
            int idx = tid + 256 * i;
            int r   = idx >> 4;          // kv pair 0..63
            int c4  = (idx & 15) * 4;    // d
            float4 v0 = *(const float4*)&Vg[(size_t)(kv0 + 2 * r) * Dm + c4];
            float4 v1 = *(const float4*)&Vg[(size_t)(kv0 + 2 * r + 1) * Dm + c4];
            PB[r * PB_STRIDE + c4 + 0] = pkbf(v0.x, v1.x);
            PB[r * PB_STRIDE + c4 + 1] = pkbf(v0.y, v1.y);
            PB[r * PB_STRIDE + c4 + 2] = pkbf(v0.z, v1.z);
            PB[r * PB_STRIDE + c4 + 3] = pkbf(v0.w, v1.w);
        }
        __syncthreads();

        // S = Q K^T  (logits already in log2 domain via pre-scale)
        float sacc[16][4];
#pragma unroll
        for (int i = 0; i < 16; i++)
#pragma unroll
            for (int j = 0; j < 4; j++) sacc[i][j] = 0.f;

#pragma unroll
        for (int kd = 0; kd < 4; kd++) {           // 16 d per step
            const int kb = kd * 8;
            unsigned a0 = Qs[rw0 * QK_STRIDE + kb + tig];
            unsigned a1 = Qs[rw1 * QK_STRIDE + kb + tig];
            unsigned a2 = Qs[rw0 * QK_STRIDE + kb + tig + 4];
            unsigned a3 = Qs[rw1 * QK_STRIDE + kb + tig + 4];
#pragma unroll
            for (int nt = 0; nt < 16; nt++) {
                unsigned b0 = Ks[(nt * 8 + g) * QK_STRIDE + kb + tig];
                unsigned b1 = Ks[(nt * 8 + g) * QK_STRIDE + kb + tig + 4];
                mma16bf(sacc[nt], a0, a1, a2, a3, b0, b1);
            }
        }

        // Online softmax (quad-lane row reduction)
        float mx0 = -1e30f, mx1 = -1e30f;
#pragma unroll
        for (int nt = 0; nt < 16; nt++) {
            mx0 = fmaxf(mx0, fmaxf(sacc[nt][0], sacc[nt][1]));
            mx1 = fmaxf(mx1, fmaxf(sacc[nt][2], sacc[nt][3]));
        }
        mx0 = fmaxf(mx0, __shfl_xor_sync(0xffffffffu, mx0, 1));
        mx0 = fmaxf(mx0, __shfl_xor_sync(0xffffffffu, mx0, 2));
        mx1 = fmaxf(mx1, __shfl_xor_sync(0xffffffffu, mx1, 1));
        mx1 = fmaxf(mx1, __shfl_xor_sync(0xffffffffu, mx1, 2));

        float mn0 = fmaxf(m0r, mx0), mn1 = fmaxf(m1r, mx1);
        float al0 = exp2f(m0r - mn0), al1 = exp2f(m1r - mn1);
        m0r = mn0; m1r = mn1;

        float sum0 = 0.f, sum1 = 0.f;
#pragma unroll
        for (int nt = 0; nt < 16; nt++) {
            float p00 = exp2f(sacc[nt][0] - mn0);
            float p01 = exp2f(sacc[nt][1] - mn0);
            float p10 = exp2f(sacc[nt][2] - mn1);
            float p11 = exp2f(sacc[nt][3] - mn1);
            sum0 += p00 + p01;
            sum1 += p10 + p11;
            sacc[nt][0] = p00; sacc[nt][1] = p01;
            sacc[nt][2] = p10; sacc[nt][3] = p11;
        }
        sum0 += __shfl_xor_sync(0xffffffffu, sum0, 1);
        sum0 += __shfl_xor_sync(0xffffffffu, sum0, 2);
        sum1 += __shfl_xor_sync(0xffffffffu, sum1, 1);
        sum1 += __shfl_xor_sync(0xffffffffu, sum1, 2);
        l0 = l0 * al0 + sum0;
        l1 = l1 * al1 + sum1;

#pragma unroll
        for (int nt = 0; nt < 8; nt++) {
            oacc[nt][0] *= al0; oacc[nt][1] *= al0;
            oacc[nt][2] *= al1; oacc[nt][3] *= al1;
        }

        // O += P V : A-fragments are direct register packs of sacc
#pragma unroll
        for (int ks = 0; ks < 8; ks++) {           // 16 kv per step
            unsigned a0 = pkbf(sacc[2 * ks][0],     sacc[2 * ks][1]);
            unsigned a1 = pkbf(sacc[2 * ks][2],     sacc[2 * ks][3]);
            unsigned a2 = pkbf(sacc[2 * ks + 1][0], sacc[2 * ks + 1][1]);
            unsigned a3 = pkbf(sacc[2 * ks + 1][2], sacc[2 * ks + 1][3]);
            const int kp0 = (8 * ks + tig) * PB_STRIDE;
            const int kp1 = (8 * ks + tig + 4) * PB_STRIDE;
#pragma unroll
            for (int nt = 0; nt < 8; nt++) {
                unsigned b0 = PB[kp0 + nt * 8 + g];
                unsigned b1 = PB[kp1 + nt * 8 + g];
                mma16bf(oacc[nt], a0, a1, a2, a3, b0, b1);
            }
        }
    }

    // Epilogue: out1 = q(fp32) + O/l
    float* Og = gO1 + ((size_t)b * SQ + q0) * Dm + h * HDIM;
    const float li0 = 1.f / l0, li1 = 1.f / l1;
#pragma unroll
    for (int nt = 0; nt < 8; nt++) {
        const int c = nt * 8 + 2 * tig;
        float2 q0v = *(const float2*)&Qg[(size_t)rw0 * Dm + c];
        float2 q1v = *(const float2*)&Qg[(size_t)rw1 * Dm + c];
        float2 o0, o1;
        o0.x = q0v.x + oacc[nt][0] * li0;
        o0.y = q0v.y + oacc[nt][1] * li0;
        o1.x = q1v.x + oacc[nt][2] * li1;
        o1.y = q1v.y + oacc[nt][3] * li1;
        *(float2*)&Og[(size_t)rw0 * Dm + c] = o0;
        *(float2*)&Og[(size_t)rw1 * Dm + c] = o1;
    }
}

// ---------------------------------------------------------------------------
extern "C" void kernel_launch(void* const* d_in, const int* in_sizes, int n_in,
                              void* d_out, int out_size)
{
    const float* query = (const float*)d_in[0];
    const float* keyv  = (const float*)d_in[1];
    const float* Wq    = (const float*)d_in[2];
    const float* bq    = (const float*)d_in[3];
    const float* Wk    = (const float*)d_in[4];
    const float* bk    = (const float*)d_in[5];
    const float* Wv    = (const float*)d_in[6];
    const float* bv    = (const float*)d_in[7];
    const float* Wo    = (const float*)d_in[8];
    const float* bo    = (const float*)d_in[9];
    float* out = (float*)d_out;

    float *qb, *kb, *vb, *o1;
    cudaGetSymbolAddress((void**)&qb, g_Q);
    cudaGetSymbolAddress((void**)&kb, g_K);
    cudaGetSymbolAddress((void**)&vb, g_V);
    cudaGetSymbolAddress((void**)&o1, g_O1);

    cudaFuncSetAttribute(flash_tc,
                         cudaFuncAttributeMaxDynamicSharedMemorySize,
                         FLASH_SMEM_BYTES);

    dim3 gq(MTOT / 128, Dm / 128, 3);   // (64, 4, 3)
    gemm_qkv<<<gq, 256>>>(query, keyv, Wq, bq, Wk, bk, Wv, bv, qb, kb, vb);

    dim3 ga(SQ / 128, 4 * NHEADS);      // (16, 32)
    flash_tc<<<ga, 256, FLASH_SMEM_BYTES>>>(qb, kb, vb, o1);

    dim3 gg(MTOT / 128, Dm / 128);      // (64, 4)
    gemm_out<<<gg, 256>>>(o1, Wo, bo, o1, out);
}

// round 6
// speedup vs baseline: 1.5612x; 1.0638x over previous
#include <cuda_runtime.h>
#include <cuda_bf16.h>
#include <math.h>

#define SQ      2048
#define Dm      512
#define NHEADS  8
#define HDIM    64
#define MTOT    8192
#define SCLOG   (0.125f * 1.44269504f)
#define CMP     1.00035f    // compensates tf32-truncation bias of raw-f32 X operand

__device__ float    g_Q  [MTOT * Dm];        // fp32 q (residual path)
__device__ unsigned g_Qb [MTOT * Dm / 2];    // bf16x2 of q*SCLOG
__device__ unsigned g_Kb [MTOT * Dm / 2];    // bf16x2 k
__device__ unsigned g_Vb [MTOT * Dm / 2];    // bf16x2 v
__device__ float    g_O1 [MTOT * Dm];
__device__ unsigned g_W32[4 * Dm * Dm];      // RN-tf32 Wq,Wk,Wv,Wo

__device__ __forceinline__ unsigned f2tf(float x) {
    unsigned u;
    asm("cvt.rna.tf32.f32 %0, %1;" : "=r"(u) : "f"(x));
    return u;
}
__device__ __forceinline__ unsigned pkbf(float lo, float hi) {
    unsigned u;
    asm("cvt.rn.bf16x2.f32 %0, %1, %2;" : "=r"(u) : "f"(hi), "f"(lo));
    return u;
}
__device__ __forceinline__ void cpasync16(unsigned saddr, const void* gptr) {
    asm volatile("cp.async.cg.shared.global [%0], [%1], 16;\n"
                 :: "r"(saddr), "l"(gptr));
}
#define CP_COMMIT() asm volatile("cp.async.commit_group;\n" ::: "memory")
#define CP_WAIT0()  asm volatile("cp.async.wait_group 0;\n" ::: "memory")

__device__ __forceinline__ void mma8(float* c, unsigned a0, unsigned a1,
                                     unsigned a2, unsigned a3,
                                     unsigned b0, unsigned b1) {
    asm volatile(
        "mma.sync.aligned.m16n8k8.row.col.f32.tf32.tf32.f32 "
        "{%0,%1,%2,%3}, {%4,%5,%6,%7}, {%8,%9}, {%0,%1,%2,%3};\n"
        : "+f"(c[0]), "+f"(c[1]), "+f"(c[2]), "+f"(c[3])
        : "r"(a0), "r"(a1), "r"(a2), "r"(a3), "r"(b0), "r"(b1));
}
__device__ __forceinline__ void mma16bf(float* c, unsigned a0, unsigned a1,
                                        unsigned a2, unsigned a3,
                                        unsigned b0, unsigned b1) {
    asm volatile(
        "mma.sync.aligned.m16n8k16.row.col.f32.bf16.bf16.f32 "
        "{%0,%1,%2,%3}, {%4,%5,%6,%7}, {%8,%9}, {%0,%1,%2,%3};\n"
        : "+f"(c[0]), "+f"(c[1]), "+f"(c[2]), "+f"(c[3])
        : "r"(a0), "r"(a1), "r"(a2), "r"(a3), "r"(b0), "r"(b1));
}

// ---------------------------------------------------------------------------
// Weight pre-conversion: fp32 -> RN tf32 (4 matrices)
// ---------------------------------------------------------------------------
__global__ void __launch_bounds__(256) cvt_weights(
    const float* __restrict__ w0, const float* __restrict__ w1,
    const float* __restrict__ w2, const float* __restrict__ w3,
    unsigned* __restrict__ dst)
{
    const float* srcs[4] = {w0, w1, w2, w3};
    const float* s = srcs[blockIdx.y];
    unsigned* d = dst + (size_t)blockIdx.y * Dm * Dm;
    int i = (blockIdx.x * 256 + threadIdx.x) * 4;
    float4 v = *(const float4*)&s[i];
    *(uint4*)&d[i] = make_uint4(f2tf(v.x), f2tf(v.y), f2tf(v.z), f2tf(v.w));
}

// ---------------------------------------------------------------------------
// cp.async double-buffered tf32 GEMM. 128x128 tile, 8 warps (4m x 2n),
// warp = 32 rows x 64 cols. X raw fp32 (HW truncates, bias compensated),
// W pre-converted RN tf32. Dynamic smem: 2 stages x (Xs[128][36]+Ws[128][36]).
// mode 0: Q  -> fp32 out + bf16(q*SCLOG)
// mode 1: KV -> bf16 out
// mode 2: final -> res + relu(acc+bias), fp32
// ---------------------------------------------------------------------------
#define GEMM_STAGE_U32 (2 * 128 * 36)
#define GEMM_SMEM_BYTES (2 * GEMM_STAGE_U32 * 4)

__device__ __forceinline__ void gemm_stage_issue(
    unsigned sb, const float* __restrict__ X, const unsigned* __restrict__ W32,
    int m0, int n0, int k0, int tid)
{
#pragma unroll
    for (int i = 0; i < 4; i++) {
        int idx = tid + 256 * i;
        int r   = idx >> 3;
        int c4  = (idx & 7) * 4;
        cpasync16(sb + (r * 36 + c4) * 4,
                  X + (size_t)(m0 + r) * Dm + k0 + c4);
        cpasync16(sb + (128 * 36 + r * 36 + c4) * 4,
                  W32 + (size_t)(n0 + r) * Dm + k0 + c4);
    }
}

__device__ __forceinline__ void gemm_body(
    const float* __restrict__ X, const unsigned* __restrict__ W32,
    const float* __restrict__ bias, const float* __restrict__ res,
    float* __restrict__ outF, unsigned* __restrict__ outB,
    int m0, int n0, int mode)
{
    extern __shared__ unsigned gsm[];
    const int tid  = threadIdx.x;
    const int wid  = tid >> 5;
    const int lane = tid & 31;
    const int g    = lane >> 2;
    const int tig  = lane & 3;
    const int wm   = wid >> 1;
    const int wn   = wid & 1;

    unsigned sbase;
    asm("{ .reg .u64 t; cvta.to.shared.u64 t, %1; cvt.u32.u64 %0, t; }"
        : "=r"(sbase) : "l"(gsm));

    float acc[2][8][4];
#pragma unroll
    for (int s = 0; s < 2; s++)
#pragma unroll
        for (int i = 0; i < 8; i++)
#pragma unroll
            for (int j = 0; j < 4; j++) acc[s][i][j] = 0.f;

    gemm_stage_issue(sbase, X, W32, m0, n0, 0, tid);
    CP_COMMIT();

    for (int st = 0; st < Dm / 32; st++) {
        CP_WAIT0();
        __syncthreads();
        if (st < Dm / 32 - 1) {
            gemm_stage_issue(sbase + ((st + 1) & 1) * GEMM_STAGE_U32 * 4,
                             X, W32, m0, n0, (st + 1) * 32, tid);
            CP_COMMIT();
        }
        unsigned* Xs = gsm + (st & 1) * GEMM_STAGE_U32;
        unsigned* Ws = Xs + 128 * 36;

#pragma unroll
        for (int kk = 0; kk < 4; kk++) {
            const int kb = kk * 8;
            unsigned a[2][4];
#pragma unroll
            for (int s = 0; s < 2; s++) {
                const int rr = wm * 32 + s * 16 + g;
                a[s][0] = Xs[rr * 36 + kb + tig];
                a[s][1] = Xs[(rr + 8) * 36 + kb + tig];
                a[s][2] = Xs[rr * 36 + kb + tig + 4];
                a[s][3] = Xs[(rr + 8) * 36 + kb + tig + 4];
            }
#pragma unroll
            for (int nt = 0; nt < 8; nt++) {
                const int nr = wn * 64 + nt * 8 + g;
                unsigned b0 = Ws[nr * 36 + kb + tig];
                unsigned b1 = Ws[nr * 36 + kb + tig + 4];
                mma8(acc[0][nt], a[0][0], a[0][1], a[0][2], a[0][3], b0, b1);
                mma8(acc[1][nt], a[1][0], a[1][1], a[1][2], a[1][3], b0, b1);
            }
        }
    }

#pragma unroll
    for (int s = 0; s < 2; s++) {
        const int r0 = m0 + wm * 32 + s * 16 + g;
        const int r1 = r0 + 8;
#pragma unroll
        for (int nt = 0; nt < 8; nt++) {
            const int n = n0 + wn * 64 + nt * 8 + 2 * tig;
            float2 bz = *(const float2*)&bias[n];
            float2 o0, o1;
            o0.x = acc[s][nt][0] * CMP + bz.x;
            o0.y = acc[s][nt][1] * CMP + bz.y;
            o1.x = acc[s][nt][2] * CMP + bz.x;
            o1.y = acc[s][nt][3] * CMP + bz.y;
            if (mode == 2) {
                float2 q0 = *(const float2*)&res[(size_t)r0 * Dm + n];
                float2 q1 = *(const float2*)&res[(size_t)r1 * Dm + n];
                o0.x = q0.x + fmaxf(o0.x, 0.f); o0.y = q0.y + fmaxf(o0.y, 0.f);
                o1.x = q1.x + fmaxf(o1.x, 0.f); o1.y = q1.y + fmaxf(o1.y, 0.f);
                *(float2*)&outF[(size_t)r0 * Dm + n] = o0;
                *(float2*)&outF[(size_t)r1 * Dm + n] = o1;
            } else if (mode == 0) {
                *(float2*)&outF[(size_t)r0 * Dm + n] = o0;
                *(float2*)&outF[(size_t)r1 * Dm + n] = o1;
                outB[(size_t)r0 * (Dm / 2) + (n >> 1)] =
                    pkbf(o0.x * SCLOG, o0.y * SCLOG);
                outB[(size_t)r1 * (Dm / 2) + (n >> 1)] =
                    pkbf(o1.x * SCLOG, o1.y * SCLOG);
            } else {
                outB[(size_t)r0 * (Dm / 2) + (n >> 1)] = pkbf(o0.x, o0.y);
                outB[(size_t)r1 * (Dm / 2) + (n >> 1)] = pkbf(o1.x, o1.y);
            }
        }
    }
}

__global__ void __launch_bounds__(256, 2) gemm_qkv(
    const float* __restrict__ query, const float* __restrict__ keyv,
    const unsigned* __restrict__ W32,
    const float* __restrict__ bq, const float* __restrict__ bk,
    const float* __restrict__ bv,
    float* __restrict__ oQ, unsigned* __restrict__ oQb,
    unsigned* __restrict__ oKb, unsigned* __restrict__ oVb)
{
    const int z = blockIdx.z;
    const float* X = (z == 0) ? query : keyv;
    const unsigned* W = W32 + (size_t)z * Dm * Dm;
    const float* B = (z == 0) ? bq : (z == 1) ? bk : bv;
    float*    oF = (z == 0) ? oQ : nullptr;
    unsigned* oB = (z == 0) ? oQb : (z == 1) ? oKb : oVb;
    gemm_body(X, W, B, nullptr, oF, oB,
              blockIdx.x * 128, blockIdx.y * 128, (z == 0) ? 0 : 1);
}

__global__ void __launch_bounds__(256, 2) gemm_out(
    const float* __restrict__ X, const unsigned* __restrict__ W32,
    const float* __restrict__ bias, const float* __restrict__ res,
    float* __restrict__ out)
{
    gemm_body(X, W32, bias, res, out, nullptr,
              blockIdx.x * 128, blockIdx.y * 128, 2);
}

// ---------------------------------------------------------------------------
// bf16 flash attention: 128q x 128kv, 8 warps, 2 CTAs/SM.
// Q/K/V arrive pre-converted bf16 (Q pre-scaled). V pair-packed via PRMT.
// ---------------------------------------------------------------------------
#define QK_STRIDE 36
#define PB_STRIDE 72
#define QS_BASE 0
#define KS_BASE (128 * QK_STRIDE)
#define PB_BASE (KS_BASE + 128 * QK_STRIDE)
#define FLASH_SMEM_U32 (PB_BASE + 64 * PB_STRIDE)
#define FLASH_SMEM_BYTES (FLASH_SMEM_U32 * 4)

__global__ void __launch_bounds__(256, 2) flash_tc(
    const unsigned* __restrict__ gQb, const unsigned* __restrict__ gKb,
    const unsigned* __restrict__ gVb, const float* __restrict__ gQ,
    float* __restrict__ gO1)
{
    extern __shared__ unsigned sm[];
    unsigned* Qs = sm + QS_BASE;   // [128][36] bf16x2 q*SCLOG
    unsigned* Ks = sm + KS_BASE;   // [128][36] bf16x2 k
    unsigned* PB = sm + PB_BASE;   // [64][72]  bf16x2 (V[2r][d], V[2r+1][d])

    const int tid  = threadIdx.x;
    const int wid  = tid >> 5;
    const int lane = tid & 31;
    const int g    = lane >> 2;
    const int tig  = lane & 3;

    const int bh = blockIdx.y;
    const int b  = bh / NHEADS;
    const int h  = bh % NHEADS;
    const int q0 = blockIdx.x * 128;

    const int Dm2 = Dm / 2;
    const unsigned* Qgb = gQb + ((size_t)b * SQ + q0) * Dm2 + h * (HDIM / 2);
    const unsigned* Kgb = gKb + (size_t)b * SQ * Dm2 + h * (HDIM / 2);
    const unsigned* Vgb = gVb + (size_t)b * SQ * Dm2 + h * (HDIM / 2);
    const float*    Qg  = gQ  + ((size_t)b * SQ + q0) * Dm + h * HDIM;

    // Stage Q once (pure copy)
#pragma unroll
    for (int i = 0; i < 4; i++) {
        int idx = tid + 256 * i;
        int r   = idx >> 3;
        int c4  = (idx & 7) * 4;
        uint4 v = *(const uint4*)&Qgb[(size_t)r * Dm2 + c4];
        *(uint4*)&Qs[r * QK_STRIDE + c4] = v;
    }

    float m0r = -1e30f, m1r = -1e30f, l0 = 0.f, l1 = 0.f;
    float oacc[8][4];
#pragma unroll
    for (int i = 0; i < 8; i++)
#pragma unroll
        for (int j = 0; j < 4; j++) oacc[i][j] = 0.f;

    const int rw0 = 16 * wid + g;
    const int rw1 = rw0 + 8;

    for (int kv0 = 0; kv0 < SQ; kv0 += 128) {
        __syncthreads();
        // K staging: pure copy
#pragma unroll
        for (int i = 0; i < 4; i++) {
            int idx = tid + 256 * i;
            int r   = idx >> 3;
            int c4  = (idx & 7) * 4;
            uint4 v = *(const uint4*)&Kgb[(size_t)(kv0 + r) * Dm2 + c4];
            *(uint4*)&Ks[r * QK_STRIDE + c4] = v;
        }
        // V staging: pair-pack rows 2r/2r+1 via PRMT
#pragma unroll
        for (int i = 0; i < 2; i++) {
            int idx = tid + 256 * i;
            int r   = idx >> 3;          // kv pair 0..63
            int c4  = (idx & 7) * 4;     // d-pair index 0..28
            const unsigned* v0p = &Vgb[(size_t)(kv0 + 2 * r) * Dm2 + c4];
            uint4 va = *(const uint4*)v0p;
            uint4 vb = *(const uint4*)(v0p + Dm2);
            unsigned vaa[4] = {va.x, va.y, va.z, va.w};
            unsigned vbb[4] = {vb.x, vb.y, vb.z, vb.w};
#pragma unroll
            for (int j = 0; j < 4; j++) {
                unsigned lo = __byte_perm(vaa[j], vbb[j], 0x5410);
                unsigned hi = __byte_perm(vaa[j], vbb[j], 0x7632);
                *(uint2*)&PB[r * PB_STRIDE + 2 * (c4 + j)] = make_uint2(lo, hi);
            }
        }
        __syncthreads();

        // S = Q K^T (logits in log2 domain via pre-scale)
        float sacc[16][4];
#pragma unroll
        for (int i = 0; i < 16; i++)
#pragma unroll
            for (int j = 0; j < 4; j++) sacc[i][j] = 0.f;

#pragma unroll
        for (int kd = 0; kd < 4; kd++) {
            const int kb = kd * 8;
            unsigned a0 = Qs[rw0 * QK_STRIDE + kb + tig];
            unsigned a1 = Qs[rw1 * QK_STRIDE + kb + tig];
            unsigned a2 = Qs[rw0 * QK_STRIDE + kb + tig + 4];
            unsigned a3 = Qs[rw1 * QK_STRIDE + kb + tig + 4];
#pragma unroll
            for (int nt = 0; nt < 16; nt++) {
                unsigned b0 = Ks[(nt * 8 + g) * QK_STRIDE + kb + tig];
                unsigned b1 = Ks[(nt * 8 + g) * QK_STRIDE + kb + tig + 4];
                mma16bf(sacc[nt], a0, a1, a2, a3, b0, b1);
            }
        }

        // Online softmax
        float mx0 = -1e30f, mx1 = -1e30f;
#pragma unroll
        for (int nt = 0; nt < 16; nt++) {
            mx0 = fmaxf(mx0, fmaxf(sacc[nt][0], sacc[nt][1]));
            mx1 = fmaxf(mx1, fmaxf(sacc[nt][2], sacc[nt][3]));
        }
        mx0 = fmaxf(mx0, __shfl_xor_sync(0xffffffffu, mx0, 1));
        mx0 = fmaxf(mx0, __shfl_xor_sync(0xffffffffu, mx0, 2));
        mx1 = fmaxf(mx1, __shfl_xor_sync(0xffffffffu, mx1, 1));
        mx1 = fmaxf(mx1, __shfl_xor_sync(0xffffffffu, mx1, 2));

        float mn0 = fmaxf(m0r, mx0), mn1 = fmaxf(m1r, mx1);
        float al0 = exp2f(m0r - mn0), al1 = exp2f(m1r - mn1);
        m0r = mn0; m1r = mn1;

        float sum0 = 0.f, sum1 = 0.f;
#pragma unroll
        for (int nt = 0; nt < 16; nt++) {
            float p00 = exp2f(sacc[nt][0] - mn0);
            float p01 = exp2f(sacc[nt][1] - mn0);
            float p10 = exp2f(sacc[nt][2] - mn1);
            float p11 = exp2f(sacc[nt][3] - mn1);
            sum0 += p00 + p01;
            sum1 += p10 + p11;
            sacc[nt][0] = p00; sacc[nt][1] = p01;
            sacc[nt][2] = p10; sacc[nt][3] = p11;
        }
        sum0 += __shfl_xor_sync(0xffffffffu, sum0, 1);
        sum0 += __shfl_xor_sync(0xffffffffu, sum0, 2);
        sum1 += __shfl_xor_sync(0xffffffffu, sum1, 1);
        sum1 += __shfl_xor_sync(0xffffffffu, sum1, 2);
        l0 = l0 * al0 + sum0;
        l1 = l1 * al1 + sum1;

#pragma unroll
        for (int nt = 0; nt < 8; nt++) {
            oacc[nt][0] *= al0; oacc[nt][1] *= al0;
            oacc[nt][2] *= al1; oacc[nt][3] *= al1;
        }

        // O += P V : A-fragments are direct register packs of sacc
#pragma unroll
        for (int ks = 0; ks < 8; ks++) {
            unsigned a0 = pkbf(sacc[2 * ks][0],     sacc[2 * ks][1]);
            unsigned a1 = pkbf(sacc[2 * ks][2],     sacc[2 * ks][3]);
            unsigned a2 = pkbf(sacc[2 * ks + 1][0], sacc[2 * ks + 1][1]);
            unsigned a3 = pkbf(sacc[2 * ks + 1][2], sacc[2 * ks + 1][3]);
            const int kp0 = (8 * ks + tig) * PB_STRIDE;
            const int kp1 = (8 * ks + tig + 4) * PB_STRIDE;
#pragma unroll
            for (int nt = 0; nt < 8; nt++) {
                unsigned b0 = PB[kp0 + nt * 8 + g];
                unsigned b1 = PB[kp1 + nt * 8 + g];
                mma16bf(oacc[nt], a0, a1, a2, a3, b0, b1);
            }
        }
    }

    // Epilogue: out1 = q(fp32) + O/l
    float* Og = gO1 + ((size_t)b * SQ + q0) * Dm + h * HDIM;
    const float li0 = 1.f / l0, li1 = 1.f / l1;
#pragma unroll
    for (int nt = 0; nt < 8; nt++) {
        const int c = nt * 8 + 2 * tig;
        float2 q0v = *(const float2*)&Qg[(size_t)rw0 * Dm + c];
        float2 q1v = *(const float2*)&Qg[(size_t)rw1 * Dm + c];
        float2 o0, o1;
        o0.x = q0v.x + oacc[nt][0] * li0;
        o0.y = q0v.y + oacc[nt][1] * li0;
        o1.x = q1v.x + oacc[nt][2] * li1;
        o1.y = q1v.y + oacc[nt][3] * li1;
        *(float2*)&Og[(size_t)rw0 * Dm + c] = o0;
        *(float2*)&Og[(size_t)rw1 * Dm + c] = o1;
    }
}

// ---------------------------------------------------------------------------
extern "C" void kernel_launch(void* const* d_in, const int* in_sizes, int n_in,
                              void* d_out, int out_size)
{
    const float* query = (const float*)d_in[0];
    const float* keyv  = (const float*)d_in[1];
    const float* Wq    = (const float*)d_in[2];
    const float* bq    = (const float*)d_in[3];
    const float* Wk    = (const float*)d_in[4];
    const float* bk    = (const float*)d_in[5];
    const float* Wv    = (const float*)d_in[6];
    const float* bv    = (const float*)d_in[7];
    const float* Wo    = (const float*)d_in[8];
    const float* bo    = (const float*)d_in[9];
    float* out = (float*)d_out;

    float *qf, *o1;
    unsigned *qb, *kb, *vb, *w32;
    cudaGetSymbolAddress((void**)&qf,  g_Q);
    cudaGetSymbolAddress((void**)&qb,  g_Qb);
    cudaGetSymbolAddress((void**)&kb,  g_Kb);
    cudaGetSymbolAddress((void**)&vb,  g_Vb);
    cudaGetSymbolAddress((void**)&o1,  g_O1);
    cudaGetSymbolAddress((void**)&w32, g_W32);

    cudaFuncSetAttribute(flash_tc,
                         cudaFuncAttributeMaxDynamicSharedMemorySize,
                         FLASH_SMEM_BYTES);
    cudaFuncSetAttribute(gemm_qkv,
                         cudaFuncAttributeMaxDynamicSharedMemorySize,
                         GEMM_SMEM_BYTES);
    cudaFuncSetAttribute(gemm_out,
                         cudaFuncAttributeMaxDynamicSharedMemorySize,
                         GEMM_SMEM_BYTES);

    dim3 gw(Dm * Dm / 1024, 4);
    cvt_weights<<<gw, 256>>>(Wq, Wk, Wv, Wo, w32);

    dim3 gq(MTOT / 128, Dm / 128, 3);   // (64, 4, 3)
    gemm_qkv<<<gq, 256, GEMM_SMEM_BYTES>>>(query, keyv, w32, bq, bk, bv,
                                           qf, qb, kb, vb);

    dim3 ga(SQ / 128, 4 * NHEADS);      // (16, 32)
    flash_tc<<<ga, 256, FLASH_SMEM_BYTES>>>(qb, kb, vb, qf, o1);

    dim3 gg(MTOT / 128, Dm / 128);      // (64, 4)
    gemm_out<<<gg, 256, GEMM_SMEM_BYTES>>>(o1, w32 + 3 * Dm * Dm, bo, o1, out);
}